// round 10
// baseline (speedup 1.0000x reference)
#include <cuda_runtime.h>
#include <cuda_bf16.h>
#include <cstdint>

typedef unsigned long long u64;
typedef unsigned int u32;

#define NTHREADS 128
#define TPB      64
#define IN_DIM   256
#define HDIM     64
#define NEXP     12

// ---- smem byte offsets (per CTA, ~100KB total -> 2 CTAs/SM) ----
#define XH_OFF   0                       // X hi A-frags: [4mt][16kt][32][16B] = 32KB
#define XL_OFF   32768
#define H1H_OFF  65536                   // h1 hi frags: [4mt][4kt][32][16B] = 8KB
#define H1L_OFF  73728
#define H2H_OFF  81920
#define H2L_OFF  90112
#define GS_OFF   98304                   // gates [64][17] fp32 = 4352B
#define SMEM_BYTES (98304 + 64*17*4)     // 102656

// ---- precomputed B fragments ----
// layout: [e][kt][8 nt][32 lane][2 u64]  (u64#0 = hi {reg0,reg1}, u64#1 = lo)
__device__ u64 g_W1f[NEXP * 16 * 8 * 32 * 2];
__device__ u64 g_W2f[NEXP * 4 * 8 * 32 * 2];
__device__ u64 g_W3f[NEXP * 4 * 8 * 32 * 2];

// ============================ helpers ============================
__device__ __forceinline__ u32 sm_addr(const void* p) {
    return (u32)__cvta_generic_to_shared(p);
}
__device__ __host__ __forceinline__ u32 packbf_h(float v0, float v1) {
#ifdef __CUDA_ARCH__
    u32 r; asm("cvt.rn.bf16x2.f32 %0, %1, %2;" : "=r"(r) : "f"(v1), "f"(v0)); return r;
#else
    return 0;
#endif
}
__device__ __forceinline__ void split_bf(float x, float& h, float& l) {
    h = __bfloat162float(__float2bfloat16_rn(x));
    l = x - h;
}
__device__ __forceinline__ void mma_bf16(float* d, const u32* a, u64 b) {
    u32 b0 = (u32)b, b1 = (u32)(b >> 32);
    asm("mma.sync.aligned.m16n8k16.row.col.f32.bf16.bf16.f32 "
        "{%0,%1,%2,%3},{%4,%5,%6,%7},{%8,%9},{%0,%1,%2,%3};"
        : "+f"(d[0]), "+f"(d[1]), "+f"(d[2]), "+f"(d[3])
        : "r"(a[0]), "r"(a[1]), "r"(a[2]), "r"(a[3]), "r"(b0), "r"(b1));
}
__device__ __forceinline__ void lds128(u32* r, u32 a) {
    asm("ld.shared.v4.b32 {%0,%1,%2,%3},[%4];"
        : "=r"(r[0]), "=r"(r[1]), "=r"(r[2]), "=r"(r[3]) : "r"(a));
}
__device__ __forceinline__ void sts128(u32 a, const u32* r) {
    asm volatile("st.shared.v4.b32 [%0],{%1,%2,%3,%4};"
        :: "r"(a), "r"(r[0]), "r"(r[1]), "r"(r[2]), "r"(r[3]));
}
__device__ __forceinline__ void ldg128_u64(const u64* p, u64& x, u64& y) {
    asm("ld.global.nc.v2.u64 {%0,%1},[%2];" : "=l"(x), "=l"(y) : "l"(p));
}

// ============================ prep kernel ============================
// u32 index r within expert region:
//   reg = r&1, part = (r>>1)&1, lane = (r>>2)&31, nt = (r>>7)&7, kt = r>>10
__global__ void prep_kernel(const float* __restrict__ Wt1, const float* __restrict__ Wt2,
                            const float* __restrict__ Wt3, const float* __restrict__ Ws1,
                            const float* __restrict__ Ws2, const float* __restrict__ Ws3) {
    int idx = blockIdx.x * blockDim.x + threadIdx.x;
    const float* W; u32* dst; int e, r;
    if (idx < NEXP * 16384) {
        e = idx >> 14; r = idx & 16383;
        W = (e < 8) ? Wt1 + e * 16384 : Ws1 + (e - 8) * 16384;
        dst = (u32*)g_W1f + e * 16384;
    } else if (idx < NEXP * 16384 + NEXP * 4096) {
        int i2 = idx - NEXP * 16384;
        e = i2 >> 12; r = i2 & 4095;
        W = (e < 8) ? Wt2 + e * 4096 : Ws2 + (e - 8) * 4096;
        dst = (u32*)g_W2f + e * 4096;
    } else if (idx < NEXP * 16384 + 2 * NEXP * 4096) {
        int i2 = idx - NEXP * 16384 - NEXP * 4096;
        e = i2 >> 12; r = i2 & 4095;
        W = (e < 8) ? Wt3 + e * 4096 : Ws3 + (e - 8) * 4096;
        dst = (u32*)g_W3f + e * 4096;
    } else return;
    int reg  = r & 1;
    int part = (r >> 1) & 1;
    int lane = (r >> 2) & 31;
    int nt   = (r >> 7) & 7;
    int kt   = r >> 10;
    int k0 = kt * 16 + reg * 8 + 2 * (lane & 3);
    int n  = nt * 8 + (lane >> 2);
    float w0 = W[k0 * 64 + n];
    float w1 = W[(k0 + 1) * 64 + n];
    float h0, l0, h1, l1;
    split_bf(w0, h0, l0); split_bf(w1, h1, l1);
    dst[r] = part ? packbf_h(l0, l1) : packbf_h(h0, h1);
}

// ============================ main kernel ============================
__global__ void __launch_bounds__(NTHREADS, 2)
mmoe_mma(const float* __restrict__ X,
         const float* __restrict__ bt1, const float* __restrict__ bt2,
         const float* __restrict__ bt3, const float* __restrict__ bs1,
         const float* __restrict__ bs2, const float* __restrict__ bs3,
         const float* __restrict__ Wg,  const float* __restrict__ bg,
         float* __restrict__ out)
{
    extern __shared__ char sm[];
    float* smf = (float*)sm;
    const int tid  = threadIdx.x;
    const int blk  = blockIdx.x;
    const int lane = tid & 31;
    const int w    = tid >> 5;
    const int wm   = w >> 1;      // 0..1 -> rows wm*32
    const int wn   = w & 1;       // 0..1 -> cols wn*32
    const u32 sb   = sm_addr(sm);

    // ---- stage Wg (16KB) into X-frag region temporarily, compute gates ----
    for (int i = tid; i < 4096 / 4; i += NTHREADS)
        ((float4*)smf)[i] = ((const float4*)Wg)[i];
    __syncthreads();
    {
        int tok = tid >> 1, t = tid & 1;
        const float* xr  = X + ((size_t)blk * TPB + tok) * IN_DIM;
        const float* wgt = smf + t * (IN_DIM * 8);
        float lg[8];
        #pragma unroll
        for (int j = 0; j < 8; j++) lg[j] = 0.f;
        #pragma unroll 4
        for (int k = 0; k < IN_DIM; k++) {
            float x = __ldg(xr + k);
            float4 w0 = *(const float4*)&wgt[k * 8];
            float4 w1 = *(const float4*)&wgt[k * 8 + 4];
            lg[0] = fmaf(x, w0.x, lg[0]); lg[1] = fmaf(x, w0.y, lg[1]);
            lg[2] = fmaf(x, w0.z, lg[2]); lg[3] = fmaf(x, w0.w, lg[3]);
            lg[4] = fmaf(x, w1.x, lg[4]); lg[5] = fmaf(x, w1.y, lg[5]);
            lg[6] = fmaf(x, w1.z, lg[6]); lg[7] = fmaf(x, w1.w, lg[7]);
        }
        float m = -1e30f;
        #pragma unroll
        for (int j = 0; j < 8; j++) { lg[j] += __ldg(bg + t * 8 + j); m = fmaxf(m, lg[j]); }
        float s = 0.f;
        #pragma unroll
        for (int j = 0; j < 8; j++) { lg[j] = expf(lg[j] - m); s += lg[j]; }
        float inv = 1.f / s;
        float* gsp = (float*)(sm + GS_OFF) + tok * 17 + t * 8;
        #pragma unroll
        for (int j = 0; j < 8; j++) gsp[j] = lg[j] * inv;
    }
    __syncthreads();

    // ---- convert X -> hi/lo A-fragments in smem ----
    {
        const float* Xb = X + (size_t)blk * TPB * IN_DIM;
        for (int i = tid; i < 4 * 16 * 32; i += NTHREADS) {
            int ln = i & 31, kt = (i >> 5) & 15, mt = i >> 9;
            int row = mt * 16 + (ln >> 2);
            int k   = kt * 16 + 2 * (ln & 3);
            float2 e0 = __ldg((const float2*)&Xb[row * IN_DIM + k]);
            float2 e1 = __ldg((const float2*)&Xb[(row + 8) * IN_DIM + k]);
            float2 e2 = __ldg((const float2*)&Xb[row * IN_DIM + k + 8]);
            float2 e3 = __ldg((const float2*)&Xb[(row + 8) * IN_DIM + k + 8]);
            float h0a,l0a,h0b,l0b, h1a,l1a,h1b,l1b;
            float h2a,l2a,h2b,l2b, h3a,l3a,h3b,l3b;
            split_bf(e0.x,h0a,l0a); split_bf(e0.y,h0b,l0b);
            split_bf(e1.x,h1a,l1a); split_bf(e1.y,h1b,l1b);
            split_bf(e2.x,h2a,l2a); split_bf(e2.y,h2b,l2b);
            split_bf(e3.x,h3a,l3a); split_bf(e3.y,h3b,l3b);
            u32 hi[4] = { packbf_h(h0a,h0b), packbf_h(h1a,h1b),
                          packbf_h(h2a,h2b), packbf_h(h3a,h3b) };
            u32 lo[4] = { packbf_h(l0a,l0b), packbf_h(l1a,l1b),
                          packbf_h(l2a,l2b), packbf_h(l3a,l3b) };
            sts128(sb + XH_OFF + i * 16, hi);
            sts128(sb + XL_OFF + i * 16, lo);
        }
    }
    __syncthreads();

    float oacc[2][2][4][4];     // [task][mt][nt][reg]
    #pragma unroll
    for (int t = 0; t < 2; t++)
        #pragma unroll
        for (int mt = 0; mt < 2; mt++)
            #pragma unroll
            for (int nt = 0; nt < 4; nt++)
                #pragma unroll
                for (int q = 0; q < 4; q++) oacc[t][mt][nt][q] = 0.f;

    const float* gsr = (const float*)(sm + GS_OFF);

    #pragma unroll 1
    for (int e = 0; e < NEXP; e++) {
        const u64* B1 = g_W1f + e * (16 * 8 * 32 * 2);
        const u64* B2 = g_W2f + e * (4 * 8 * 32 * 2);
        const u64* B3 = g_W3f + e * (4 * 8 * 32 * 2);
        const float* b1 = (e < 8) ? bt1 + e * 64 : bs1 + (e - 8) * 64;
        const float* b2 = (e < 8) ? bt2 + e * 64 : bs2 + (e - 8) * 64;
        const float* b3 = (e < 8) ? bt3 + e * 64 : bs3 + (e - 8) * 64;

        float acc[2][4][4];     // [mt][nt][reg]

        // ================= Layer 1 (K=256, 16 ktiles) =================
        #pragma unroll
        for (int mt = 0; mt < 2; mt++)
            #pragma unroll
            for (int nt = 0; nt < 4; nt++)
                #pragma unroll
                for (int q = 0; q < 4; q++) acc[mt][nt][q] = 0.f;

        #pragma unroll 2
        for (int kt = 0; kt < 16; kt++) {
            u32 ah[2][4], al[2][4];
            #pragma unroll
            for (int mt = 0; mt < 2; mt++) {
                u32 off = (u32)((((wm * 2 + mt) * 16 + kt) * 32 + lane) * 16);
                lds128(ah[mt], sb + XH_OFF + off);
                lds128(al[mt], sb + XL_OFF + off);
            }
            u64 bh[4], bl[4];
            #pragma unroll
            for (int nt = 0; nt < 4; nt++)
                ldg128_u64(B1 + ((kt * 8 + wn * 4 + nt) * 32 + lane) * 2, bh[nt], bl[nt]);
            #pragma unroll
            for (int nt = 0; nt < 4; nt++) {
                mma_bf16(acc[0][nt], ah[0], bh[nt]);
                mma_bf16(acc[1][nt], ah[1], bh[nt]);
            }
            #pragma unroll
            for (int nt = 0; nt < 4; nt++) {
                mma_bf16(acc[0][nt], al[0], bh[nt]);
                mma_bf16(acc[1][nt], al[1], bh[nt]);
            }
            #pragma unroll
            for (int nt = 0; nt < 4; nt++) {
                mma_bf16(acc[0][nt], ah[0], bl[nt]);
                mma_bf16(acc[1][nt], ah[1], bl[nt]);
            }
        }
        // epilogue -> h1 frags: warp covers ktiles wn*2+p of next layer
        #pragma unroll
        for (int mt = 0; mt < 2; mt++) {
            #pragma unroll
            for (int p = 0; p < 2; p++) {
                u32 hi[4], lo[4];
                #pragma unroll
                for (int q = 0; q < 2; q++) {
                    int nt = p * 2 + q;
                    int col = wn * 32 + nt * 8 + 2 * (lane & 3);
                    float2 bb = __ldg((const float2*)&b1[col]);
                    float v0 = fmaxf(acc[mt][nt][0] + bb.x, 0.f);
                    float v1 = fmaxf(acc[mt][nt][1] + bb.y, 0.f);
                    float v2 = fmaxf(acc[mt][nt][2] + bb.x, 0.f);
                    float v3 = fmaxf(acc[mt][nt][3] + bb.y, 0.f);
                    float h0,l0,h1,l1,h2,l2,h3,l3;
                    split_bf(v0,h0,l0); split_bf(v1,h1,l1);
                    split_bf(v2,h2,l2); split_bf(v3,h3,l3);
                    hi[q * 2]     = packbf_h(h0, h1);
                    hi[q * 2 + 1] = packbf_h(h2, h3);
                    lo[q * 2]     = packbf_h(l0, l1);
                    lo[q * 2 + 1] = packbf_h(l2, l3);
                }
                u32 off = (u32)((((wm * 2 + mt) * 4 + wn * 2 + p) * 32 + lane) * 16);
                sts128(sb + H1H_OFF + off, hi);
                sts128(sb + H1L_OFF + off, lo);
            }
        }
        __syncthreads();

        // ================= Layer 2 (K=64, 4 ktiles) =================
        #pragma unroll
        for (int mt = 0; mt < 2; mt++)
            #pragma unroll
            for (int nt = 0; nt < 4; nt++)
                #pragma unroll
                for (int q = 0; q < 4; q++) acc[mt][nt][q] = 0.f;
        #pragma unroll
        for (int kt = 0; kt < 4; kt++) {
            u32 ah[2][4], al[2][4];
            #pragma unroll
            for (int mt = 0; mt < 2; mt++) {
                u32 off = (u32)((((wm * 2 + mt) * 4 + kt) * 32 + lane) * 16);
                lds128(ah[mt], sb + H1H_OFF + off);
                lds128(al[mt], sb + H1L_OFF + off);
            }
            u64 bh[4], bl[4];
            #pragma unroll
            for (int nt = 0; nt < 4; nt++)
                ldg128_u64(B2 + ((kt * 8 + wn * 4 + nt) * 32 + lane) * 2, bh[nt], bl[nt]);
            #pragma unroll
            for (int nt = 0; nt < 4; nt++) {
                mma_bf16(acc[0][nt], ah[0], bh[nt]);
                mma_bf16(acc[1][nt], ah[1], bh[nt]);
            }
            #pragma unroll
            for (int nt = 0; nt < 4; nt++) {
                mma_bf16(acc[0][nt], al[0], bh[nt]);
                mma_bf16(acc[1][nt], al[1], bh[nt]);
            }
            #pragma unroll
            for (int nt = 0; nt < 4; nt++) {
                mma_bf16(acc[0][nt], ah[0], bl[nt]);
                mma_bf16(acc[1][nt], ah[1], bl[nt]);
            }
        }
        #pragma unroll
        for (int mt = 0; mt < 2; mt++) {
            #pragma unroll
            for (int p = 0; p < 2; p++) {
                u32 hi[4], lo[4];
                #pragma unroll
                for (int q = 0; q < 2; q++) {
                    int nt = p * 2 + q;
                    int col = wn * 32 + nt * 8 + 2 * (lane & 3);
                    float2 bb = __ldg((const float2*)&b2[col]);
                    float v0 = fmaxf(acc[mt][nt][0] + bb.x, 0.f);
                    float v1 = fmaxf(acc[mt][nt][1] + bb.y, 0.f);
                    float v2 = fmaxf(acc[mt][nt][2] + bb.x, 0.f);
                    float v3 = fmaxf(acc[mt][nt][3] + bb.y, 0.f);
                    float h0,l0,h1,l1,h2,l2,h3,l3;
                    split_bf(v0,h0,l0); split_bf(v1,h1,l1);
                    split_bf(v2,h2,l2); split_bf(v3,h3,l3);
                    hi[q * 2]     = packbf_h(h0, h1);
                    hi[q * 2 + 1] = packbf_h(h2, h3);
                    lo[q * 2]     = packbf_h(l0, l1);
                    lo[q * 2 + 1] = packbf_h(l2, l3);
                }
                u32 off = (u32)((((wm * 2 + mt) * 4 + wn * 2 + p) * 32 + lane) * 16);
                sts128(sb + H2H_OFF + off, hi);
                sts128(sb + H2L_OFF + off, lo);
            }
        }
        __syncthreads();

        // ================= Layer 3 (K=64) + gated combine =================
        #pragma unroll
        for (int mt = 0; mt < 2; mt++)
            #pragma unroll
            for (int nt = 0; nt < 4; nt++)
                #pragma unroll
                for (int q = 0; q < 4; q++) acc[mt][nt][q] = 0.f;
        #pragma unroll
        for (int kt = 0; kt < 4; kt++) {
            u32 ah[2][4], al[2][4];
            #pragma unroll
            for (int mt = 0; mt < 2; mt++) {
                u32 off = (u32)((((wm * 2 + mt) * 4 + kt) * 32 + lane) * 16);
                lds128(ah[mt], sb + H2H_OFF + off);
                lds128(al[mt], sb + H2L_OFF + off);
            }
            u64 bh[4], bl[4];
            #pragma unroll
            for (int nt = 0; nt < 4; nt++)
                ldg128_u64(B3 + ((kt * 8 + wn * 4 + nt) * 32 + lane) * 2, bh[nt], bl[nt]);
            #pragma unroll
            for (int nt = 0; nt < 4; nt++) {
                mma_bf16(acc[0][nt], ah[0], bh[nt]);
                mma_bf16(acc[1][nt], ah[1], bh[nt]);
            }
            #pragma unroll
            for (int nt = 0; nt < 4; nt++) {
                mma_bf16(acc[0][nt], al[0], bh[nt]);
                mma_bf16(acc[1][nt], al[1], bh[nt]);
            }
            #pragma unroll
            for (int nt = 0; nt < 4; nt++) {
                mma_bf16(acc[0][nt], ah[0], bl[nt]);
                mma_bf16(acc[1][nt], ah[1], bl[nt]);
            }
        }
        // gates: 4 rows per thread (2 mt x {r, r+8})
        float g0r[2][2], g1r[2][2];
        #pragma unroll
        for (int mt = 0; mt < 2; mt++) {
            #pragma unroll
            for (int rh = 0; rh < 2; rh++) {
                int row = wm * 32 + mt * 16 + (lane >> 2) + rh * 8;
                float a, b;
                if (e < 8) {
                    int t = e >> 2, ix = e & 3;
                    float g = gsr[row * 17 + t * 8 + ix];
                    a = t ? 0.f : g;
                    b = t ? g : 0.f;
                } else {
                    int sx = e - 8;
                    a = gsr[row * 17 + 4 + sx];
                    b = gsr[row * 17 + 12 + sx];
                }
                g0r[mt][rh] = a; g1r[mt][rh] = b;
            }
        }
        #pragma unroll
        for (int mt = 0; mt < 2; mt++) {
            #pragma unroll
            for (int nt = 0; nt < 4; nt++) {
                int col = wn * 32 + nt * 8 + 2 * (lane & 3);
                float2 bb = __ldg((const float2*)&b3[col]);
                float v0 = acc[mt][nt][0] + bb.x;
                float v1 = acc[mt][nt][1] + bb.y;
                float v2 = acc[mt][nt][2] + bb.x;
                float v3 = acc[mt][nt][3] + bb.y;
                oacc[0][mt][nt][0] = fmaf(g0r[mt][0], v0, oacc[0][mt][nt][0]);
                oacc[0][mt][nt][1] = fmaf(g0r[mt][0], v1, oacc[0][mt][nt][1]);
                oacc[0][mt][nt][2] = fmaf(g0r[mt][1], v2, oacc[0][mt][nt][2]);
                oacc[0][mt][nt][3] = fmaf(g0r[mt][1], v3, oacc[0][mt][nt][3]);
                oacc[1][mt][nt][0] = fmaf(g1r[mt][0], v0, oacc[1][mt][nt][0]);
                oacc[1][mt][nt][1] = fmaf(g1r[mt][0], v1, oacc[1][mt][nt][1]);
                oacc[1][mt][nt][2] = fmaf(g1r[mt][1], v2, oacc[1][mt][nt][2]);
                oacc[1][mt][nt][3] = fmaf(g1r[mt][1], v3, oacc[1][mt][nt][3]);
            }
        }
        __syncthreads();
    }

    // ---- write output [B, 2, 64] ----
    float* ob = out + (size_t)blk * TPB * 128;
    #pragma unroll
    for (int t = 0; t < 2; t++) {
        #pragma unroll
        for (int mt = 0; mt < 2; mt++) {
            #pragma unroll
            for (int rh = 0; rh < 2; rh++) {
                int row = wm * 32 + mt * 16 + (lane >> 2) + rh * 8;
                #pragma unroll
                for (int nt = 0; nt < 4; nt++) {
                    int col = wn * 32 + nt * 8 + 2 * (lane & 3);
                    float2 v = make_float2(oacc[t][mt][nt][rh * 2],
                                           oacc[t][mt][nt][rh * 2 + 1]);
                    *(float2*)&ob[row * 128 + t * 64 + col] = v;
                }
            }
        }
    }
}

// ============================ launch ============================
extern "C" void kernel_launch(void* const* d_in, const int* in_sizes, int n_in,
                              void* d_out, int out_size) {
    const float* X   = (const float*)d_in[0];
    const float* Wt1 = (const float*)d_in[1];
    const float* bt1 = (const float*)d_in[2];
    const float* Wt2 = (const float*)d_in[3];
    const float* bt2 = (const float*)d_in[4];
    const float* Wt3 = (const float*)d_in[5];
    const float* bt3 = (const float*)d_in[6];
    const float* Ws1 = (const float*)d_in[7];
    const float* bs1 = (const float*)d_in[8];
    const float* Ws2 = (const float*)d_in[9];
    const float* bs2 = (const float*)d_in[10];
    const float* Ws3 = (const float*)d_in[11];
    const float* bs3 = (const float*)d_in[12];
    const float* Wg  = (const float*)d_in[13];
    const float* bg  = (const float*)d_in[14];
    float* out = (float*)d_out;

    int B = in_sizes[0] / IN_DIM;          // 65536
    int grid = B / TPB;                    // 1024

    int prep_total = NEXP * 16384 + 2 * NEXP * 4096;   // 294912
    prep_kernel<<<(prep_total + 255) / 256, 256>>>(Wt1, Wt2, Wt3, Ws1, Ws2, Ws3);

    cudaFuncSetAttribute(mmoe_mma, cudaFuncAttributeMaxDynamicSharedMemorySize, SMEM_BYTES);
    mmoe_mma<<<grid, NTHREADS, SMEM_BYTES>>>(
        X, bt1, bt2, bt3, bs1, bs2, bs3, Wg, bg, out);
}